// round 4
// baseline (speedup 1.0000x reference)
#include <cuda_runtime.h>
#include <math.h>
#include <stdint.h>

// ---------------------------------------------------------------------------
// YOLO loss, fused single kernel. Bitmap prefilter + 4-wide dense quads +
// warp-per-pair positives. B=8, A=3, M=64 targets, 80 classes.
// ---------------------------------------------------------------------------

#define NBATCH 8
#define MTGT   64
#define NCLS   80
#define NCHAN  85
#define NPAIR  (3 * MTGT * 3)   // 576
#define MAXW   76
#define BMW    3                // bitmap words per row (76 bits -> 3 u32)

__device__ __constant__ float C_INV[3]  = {0.125f, 0.0625f, 0.03125f};
__device__ __constant__ float C_XYS[3]  = {1.2f, 1.1f, 1.05f};
__device__ __constant__ float C_AW[3][3] = {
    {1.5f, 2.375f, 5.0f},
    {2.25f, 4.75f, 4.5f},
    {4.4375f, 6.0f, 14.34375f}};
__device__ __constant__ float C_AH[3][3] = {
    {2.0f, 4.5f, 3.5f},
    {4.6875f, 3.4375f, 9.125f},
    {3.4375f, 7.59375f, 12.53125f}};

// block layout: L0 quads 136, L1 quads 34, L2 scalar 34
#define NBLK0  136
#define NBLK1  34
#define NBLK2  34
#define NBLK_TOTAL (NBLK0 + NBLK1 + NBLK2)   // 204

__device__ double   g_negpart[NBLK_TOTAL];
__device__ double   g_posiou[NPAIR];
__device__ double   g_posobj[NPAIR];
__device__ double   g_poscls[NPAIR];
__device__ unsigned g_done = 0;

// ---------------------------------------------------------------------------
__device__ __forceinline__ float softplus_fast(float x) {
    return fmaxf(x, 0.0f) + __logf(1.0f + __expf(-fabsf(x)));
}

struct TPrep {
    float4 corn;   // x1,y1,x2,y2 (grid units)
    float4 cwh;    // cx, cy, wx, wy
    float  area;
    int    meta;   // bid | ti<<4 | tj<<12 | matchbits<<20
};

// EXACT fp32 (div by power-of-2 -> exact multiply), same op order as reference
__device__ __forceinline__ TPrep prep_one(int L, int t,
                                          const float* __restrict__ targets) {
    float inv = C_INV[L];
    float x1 = targets[t * 5 + 0] * inv;
    float y1 = targets[t * 5 + 1] * inv;
    float x2 = targets[t * 5 + 2] * inv;
    float y2 = targets[t * 5 + 3] * inv;
    int bid  = (int)targets[t * 5 + 4];

    float wx = x2 - x1, wy = y2 - y1;
    float cx = (x1 + x2) * 0.5f, cy = (y1 + y2) * 0.5f;
    int ti = (int)cx, tj = (int)cy;
    float tarea = wx * wy;

    float iou[3];
    #pragma unroll
    for (int a = 0; a < 3; ++a) {
        float aw = C_AW[L][a], ah = C_AH[L][a];
        float inter = fminf(aw, wx) * fminf(ah, wy);
        iou[a] = inter / ((aw * ah + tarea) - inter);   // IEEE div: threshold-critical
    }
    int best = 0;
    if (iou[1] > iou[best]) best = 1;
    if (iou[2] > iou[best]) best = 2;
    int mb = 0;
    #pragma unroll
    for (int a = 0; a < 3; ++a)
        if (iou[a] > 0.213f || a == best) mb |= (1 << a);

    TPrep p;
    p.corn = make_float4(cx - wx * 0.5f, cy - wy * 0.5f,
                         cx + wx * 0.5f, cy + wy * 0.5f);
    p.cwh  = make_float4(cx, cy, wx, wy);
    p.area = tarea;
    p.meta = bid | (ti << 4) | (tj << 12) | (mb << 20);
    return p;
}

// CIoU (forward)
__device__ __forceinline__ float ciou_f(
    float cx1, float cy1, float w1, float h1,
    float cx2, float cy2, float w2, float h2) {
    float b1x1 = cx1 - 0.5f * w1, b1x2 = cx1 + 0.5f * w1;
    float b1y1 = cy1 - 0.5f * h1, b1y2 = cy1 + 0.5f * h1;
    float b2x1 = cx2 - 0.5f * w2, b2x2 = cx2 + 0.5f * w2;
    float b2y1 = cy2 - 0.5f * h2, b2y2 = cy2 + 0.5f * h2;
    float iw = fminf(b1x2, b2x2) - fmaxf(b1x1, b2x1);
    float ih = fminf(b1y2, b2y2) - fmaxf(b1y1, b2y1);
    float inter = fmaxf(iw, 0.0f) * fmaxf(ih, 0.0f);
    float uni = w1 * h1 + w2 * h2 + 1e-16f - inter;
    float iou = inter / uni;
    float cw = fmaxf(b1x2, b2x2) - fminf(b1x1, b2x1);
    float ch = fmaxf(b1y2, b2y2) - fminf(b1y1, b2y1);
    float c2 = cw * cw + ch * ch + 1e-16f;
    float rho2 = (cx1 - cx2) * (cx1 - cx2) + (cy1 - cy2) * (cy1 - cy2);
    float d = atanf(w2 / h2) - atanf(w1 / h1);
    float v = (float)(4.0 / (M_PI * M_PI)) * d * d;
    float alpha = v / ((1.0f - iou) + v + 1e-16f);
    return iou - (rho2 / c2 + v * alpha);
}

// full exact test for a candidate cell: returns true if neg weight is 0
__device__ __forceinline__ bool cell_is_zero(
    const float* __restrict__ pred, int chan, int HW_, int lc,
    int x, int y, int a, int b, float s, float half_sm1, float aw, float ah,
    const float4* __restrict__ sc, const float* __restrict__ sa,
    const int*    __restrict__ sk, const int4*  __restrict__ spf,
    const int*    __restrict__ soff) {

    float p0 = pred[chan + lc];
    float p1 = pred[chan + HW_ + lc];
    float p2 = pred[chan + 2 * HW_ + lc];
    float p3 = pred[chan + 3 * HW_ + lc];

    float bx = __fdividef(1.0f, 1.0f + __expf(-p0)) * s - half_sm1;
    float by = __fdividef(1.0f, 1.0f + __expf(-p1)) * s - half_sm1;
    float pw = __expf(p2) * aw;
    float ph = __expf(p3) * ah;

    float cxa = bx + (float)x;
    float cya = by + (float)y;
    float bx1 = cxa - 0.5f * pw, bx2 = cxa + 0.5f * pw;
    float by1 = cya - 0.5f * ph, by2 = cya + 0.5f * ph;
    float parea = pw * ph;

    int mykey = x | (y << 8);
    int kend = soff[b + 1];
    for (int k = soff[b]; k < kend; ++k) {
        int4 pf = spf[k];
        if (x < pf.x || x > pf.y || y < pf.z || y > pf.w) continue;
        int kk = sk[k];
        if (((kk & 0xFFFF) == mykey) && ((kk >> (16 + a)) & 1)) return true;
        float4 c  = sc[k];
        float ix = fminf(bx2, c.z) - fmaxf(bx1, c.x);
        float iy = fminf(by2, c.w) - fmaxf(by1, c.y);
        float inter = fmaxf(ix, 0.0f) * fmaxf(iy, 0.0f);
        float uni   = (parea + sa[k] + 1e-16f) - inter;
        if (inter > 0.7f * uni) return true;
    }
    return false;
}

// 4 consecutive linear cells in one (b,a) plane
template<int W, int HW>
__device__ __forceinline__ float dense_quads(
    const float* __restrict__ pred, int qi, int L, float s, float half_sm1,
    const uint32_t (* __restrict__ bm)[MAXW][BMW],
    const float4* __restrict__ sc, const float* __restrict__ sa,
    const int*    __restrict__ sk, const int4*  __restrict__ spf,
    const int*    __restrict__ soff) {

    constexpr int QPP = HW / 4;
    if (qi >= 24 * QPP) return 0.0f;
    int plane = qi / QPP;
    int r  = qi - plane * QPP;
    int lc = r * 4;
    int y0 = lc / W;
    int x0 = lc - y0 * W;
    int a  = plane % 3;
    int b  = plane / 3;
    int chan = plane * (NCHAN * HW);
    float aw = C_AW[L][a], ah = C_AH[L][a];

    const float4 po4 = *reinterpret_cast<const float4*>(pred + chan + 4 * HW + lc);
    float po[4] = {po4.x, po4.y, po4.z, po4.w};

    int xs[4], ys[4];
    #pragma unroll
    for (int j = 0; j < 4; ++j) {
        int xx = x0 + j, yy = y0;
        if (xx >= W) { xx -= W; yy += 1; }
        xs[j] = xx; ys[j] = yy;
    }

    int mask = 0;
    #pragma unroll
    for (int j = 0; j < 4; ++j)
        if ((bm[b][ys[j]][xs[j] >> 5] >> (xs[j] & 31)) & 1u) mask |= (1 << j);

    float sum = 0.0f;
    if (mask == 0) {
        sum = softplus_fast(po[0]) + softplus_fast(po[1])
            + softplus_fast(po[2]) + softplus_fast(po[3]);
    } else {
        #pragma unroll
        for (int j = 0; j < 4; ++j) {
            bool zero = false;
            if ((mask >> j) & 1)
                zero = cell_is_zero(pred, chan, HW, lc + j, xs[j], ys[j], a, b,
                                    s, half_sm1, aw, ah, sc, sa, sk, spf, soff);
            if (!zero) sum += softplus_fast(po[j]);
        }
    }
    return sum;
}

// scalar path (W=19: HW odd)
template<int W, int HW>
__device__ __forceinline__ float dense_scalar(
    const float* __restrict__ pred, int idx, int L, float s, float half_sm1,
    const uint32_t (* __restrict__ bm)[MAXW][BMW],
    const float4* __restrict__ sc, const float* __restrict__ sa,
    const int*    __restrict__ sk, const int4*  __restrict__ spf,
    const int*    __restrict__ soff) {

    if (idx >= 24 * HW) return 0.0f;
    int plane = idx / HW;
    int lc = idx - plane * HW;
    int y = lc / W;
    int x = lc - y * W;
    int a = plane % 3;
    int b = plane / 3;
    int chan = plane * (NCHAN * HW);
    float po = pred[chan + 4 * HW + lc];

    bool zero = false;
    if ((bm[b][y][x >> 5] >> (x & 31)) & 1u)
        zero = cell_is_zero(pred, chan, HW, lc, x, y, a, b, s, half_sm1,
                            C_AW[L][a], C_AH[L][a], sc, sa, sk, spf, soff);
    return zero ? 0.0f : softplus_fast(po);
}

// ---------------------------------------------------------------------------
__global__ void __launch_bounds__(256) yolo_fused_kernel(
    const float* __restrict__ pred0,
    const float* __restrict__ pred1,
    const float* __restrict__ pred2,
    const float* __restrict__ targets,
    const int*   __restrict__ cats,
    float* __restrict__ out) {

    int L, blk;
    if (blockIdx.x >= NBLK0 + NBLK1)      { L = 2; blk = blockIdx.x - (NBLK0 + NBLK1); }
    else if (blockIdx.x >= NBLK0)         { L = 1; blk = blockIdx.x - NBLK0; }
    else                                  { L = 0; blk = blockIdx.x; }

    const float* pred = (L == 0) ? pred0 : ((L == 1) ? pred1 : pred2);
    int W_rt = (L == 0) ? 76 : ((L == 1) ? 38 : 19);
    float s = C_XYS[L];
    float half_sm1 = 0.5f * (s - 1.0f);

    int tid  = threadIdx.x;
    int lane = tid & 31;
    int wid  = tid >> 5;

    // ---- shared ------------------------------------------------------------
    __shared__ uint32_t s_bm[NBATCH][MAXW][BMW];   // candidate bitmap
    __shared__ float4 s_corn[MTGT];
    __shared__ float  s_area[MTGT];
    __shared__ int    s_key [MTGT];
    __shared__ int4   s_pf  [MTGT];                // xlo,xhi,ylo,yhi
    __shared__ int    s_cnt[NBATCH], s_fill[NBATCH], s_off[NBATCH + 1];

    // zero bitmap + counters
    for (int i = tid; i < NBATCH * MAXW * BMW; i += 256)
        ((uint32_t*)s_bm)[i] = 0u;
    if (tid < NBATCH) { s_cnt[tid] = 0; s_fill[tid] = 0; }
    __syncthreads();

    // prep + paint
    TPrep myp;
    int4 mybox;
    if (tid < MTGT) {
        myp = prep_one(L, tid, targets);
        int b = myp.meta & 15;
        atomicAdd(&s_cnt[b], 1);
        // conservative candidate box (sound superset; see derivation)
        float tw = myp.cwh.z, th = myp.cwh.w;
        float mx = 0.34f * tw + 1.3f;
        float my = 0.34f * th + 1.3f;
        int xlo = max(0,        (int)floorf(myp.corn.x - mx));
        int xhi = min(W_rt - 1, (int)ceilf (myp.corn.z + mx));
        int ylo = max(0,        (int)floorf(myp.corn.y - my));
        int yhi = min(W_rt - 1, (int)ceilf (myp.corn.w + my));
        mybox = make_int4(xlo, xhi, ylo, yhi);
        // paint bitmap rows
        if (xlo <= xhi) {
            int w0 = xlo >> 5, w1 = xhi >> 5;
            for (int yy = ylo; yy <= yhi; ++yy)
                for (int ww = w0; ww <= w1; ++ww) {
                    int lob = (ww == w0) ? (xlo & 31) : 0;
                    int hib = (ww == w1) ? (xhi & 31) : 31;
                    uint32_t bits = (hib == 31) ? (~0u << lob)
                                                : (((1u << (hib + 1)) - 1u) & (~0u << lob));
                    atomicOr(&s_bm[b][yy][ww], bits);
                }
        }
    }
    __syncthreads();
    if (tid == 0) {
        int acc = 0;
        #pragma unroll
        for (int i = 0; i < NBATCH; ++i) { s_off[i] = acc; acc += s_cnt[i]; }
        s_off[NBATCH] = acc;
    }
    __syncthreads();
    if (tid < MTGT) {
        int b = myp.meta & 15;
        int pos = s_off[b] + atomicAdd(&s_fill[b], 1);
        s_corn[pos] = myp.corn;
        s_area[pos] = myp.area;
        s_key [pos] = ((myp.meta >> 4) & 255) | (((myp.meta >> 12) & 255) << 8)
                    | (((myp.meta >> 20) & 7) << 16);
        s_pf [pos]  = mybox;
    }
    __syncthreads();

    // ---- dense phase ---------------------------------------------------------
    float local;
    if (L == 0)
        local = dense_quads<76, 5776>(pred, blk * 256 + tid, 0, s, half_sm1,
                                      s_bm, s_corn, s_area, s_key, s_pf, s_off);
    else if (L == 1)
        local = dense_quads<38, 1444>(pred, blk * 256 + tid, 1, s, half_sm1,
                                      s_bm, s_corn, s_area, s_key, s_pf, s_off);
    else
        local = dense_scalar<19, 361>(pred, blk * 256 + tid, 2, s, half_sm1,
                                      s_bm, s_corn, s_area, s_key, s_pf, s_off);

    // ---- block reduce (double, deterministic) ---------------------------------
    {
        double v = (double)local;
        #pragma unroll
        for (int o = 16; o > 0; o >>= 1)
            v += __shfl_down_sync(0xFFFFFFFFu, v, o);
        __shared__ double wsum[8];
        if (lane == 0) wsum[wid] = v;
        __syncthreads();
        if (tid == 0) {
            double t2 = 0.0;
            #pragma unroll
            for (int i = 0; i < 8; ++i) t2 += wsum[i];
            g_negpart[blockIdx.x] = t2;
        }
    }

    // ---- positives: one warp per (L,t,a) pair ----------------------------------
    int gw = blockIdx.x * 8 + wid;
    if (gw < NPAIR) {
        int FL  = gw / (MTGT * 3);
        int rem = gw % (MTGT * 3);
        int t   = rem / 3;
        int a   = rem % 3;

        TPrep pp = prep_one(FL, t, targets);   // all lanes, uniform
        bool matched = (pp.meta >> (20 + a)) & 1;

        double iou_d = 0.0, obj_d = 0.0, cls_d = 0.0;
        if (matched) {
            int bid = pp.meta & 15;
            int ti  = (pp.meta >> 4) & 255;
            int tj  = (pp.meta >> 12) & 255;
            const float* fp = (FL == 0) ? pred0 : ((FL == 1) ? pred1 : pred2);
            int fw  = (FL == 0) ? 76 : ((FL == 1) ? 38 : 19);
            int fhw = fw * fw;
            int base = ((bid * 3 + a) * NCHAN) * fhw + tj * fw + ti;

            float cls_acc = 0.0f;
            int cat = cats[t] - 1;
            for (int c = lane; c < NCLS; c += 32) {
                float xl  = fp[base + (5 + c) * fhw];
                float bce = softplus_fast(xl);
                if (c == cat) bce -= xl;
                cls_acc += bce;
            }
            #pragma unroll
            for (int o = 16; o > 0; o >>= 1)
                cls_acc += __shfl_down_sync(0xFFFFFFFFu, cls_acc, o);

            if (lane == 0) {
                float fs  = C_XYS[FL];
                float fhs = 0.5f * (fs - 1.0f);
                float p0 = fp[base];
                float p1 = fp[base + fhw];
                float p2 = fp[base + 2 * fhw];
                float p3 = fp[base + 3 * fhw];
                float po = fp[base + 4 * fhw];

                float bx = __fdividef(1.0f, 1.0f + __expf(-p0)) * fs - fhs;
                float by = __fdividef(1.0f, 1.0f + __expf(-p1)) * fs - fhs;
                float pw = __expf(p2) * C_AW[FL][a];
                float ph = __expf(p3) * C_AH[FL][a];

                float fx = pp.cwh.x - (float)ti;
                float fy = pp.cwh.y - (float)tj;
                iou_d = (double)(1.0f - ciou_f(bx, by, pw, ph, fx, fy,
                                               pp.cwh.z, pp.cwh.w));
                obj_d = (double)(softplus_fast(po) - po);
                cls_d = (double)cls_acc;
            }
        }
        if (lane == 0) {
            g_posiou[gw] = iou_d;
            g_posobj[gw] = obj_d;
            g_poscls[gw] = cls_d;
        }
    }

    // ---- elect last block --------------------------------------------------------
    __shared__ int s_last;
    if (tid == 0) {
        __threadfence();
        unsigned old = atomicAdd(&g_done, 1u);
        s_last = (old == NBLK_TOTAL - 1) ? 1 : 0;
    }
    __syncthreads();
    if (!s_last) return;
    __threadfence();

    // ---- final reduction (last block) ----------------------------------------------
    double iou_s = 0.0, obj_s = 0.0, cls_s = 0.0, neg_s = 0.0;
    for (int i = tid; i < NBLK_TOTAL; i += 256) neg_s += g_negpart[i];
    for (int i = tid; i < NPAIR; i += 256) {
        iou_s += g_posiou[i];
        obj_s += g_posobj[i];
        cls_s += g_poscls[i];
    }

    __shared__ double fred[8][4];
    double vals[4] = {iou_s, obj_s, cls_s, neg_s};
    #pragma unroll
    for (int q = 0; q < 4; ++q) {
        double v = vals[q];
        #pragma unroll
        for (int o = 16; o > 0; o >>= 1)
            v += __shfl_down_sync(0xFFFFFFFFu, v, o);
        if (lane == 0) fred[wid][q] = v;
    }
    __syncthreads();
    if (tid == 0) {
        double tot[4] = {0.0, 0.0, 0.0, 0.0};
        #pragma unroll
        for (int i = 0; i < 8; ++i) {
            tot[0] += fred[i][0];
            tot[1] += fred[i][1];
            tot[2] += fred[i][2];
            tot[3] += fred[i][3];
        }
        out[0] = (float)(0.07 * tot[0]);
        out[1] = (float)(tot[1] + tot[3]);
        out[2] = (float)(tot[2]);
        g_done = 0;
    }
}

// ---------------------------------------------------------------------------
extern "C" void kernel_launch(void* const* d_in, const int* in_sizes, int n_in,
                              void* d_out, int out_size) {
    const float* pred0   = (const float*)d_in[0];
    const float* pred1   = (const float*)d_in[1];
    const float* pred2   = (const float*)d_in[2];
    const float* targets = (const float*)d_in[3];
    const int*   cats    = (const int*)  d_in[4];
    float* out = (float*)d_out;

    yolo_fused_kernel<<<NBLK_TOTAL, 256>>>(pred0, pred1, pred2, targets, cats, out);
}

// round 5
// speedup vs baseline: 1.1479x; 1.1479x over previous
#include <cuda_runtime.h>
#include <math.h>
#include <stdint.h>

// ---------------------------------------------------------------------------
// YOLO loss, fused single kernel. 1 cell/thread (high occupancy) + O(1)
// shared-bitmap prefilter + warp-per-pair positives.
// B=8, A=3, M=64 targets, 80 classes, grids 76/38/19.
// ---------------------------------------------------------------------------

#define NBATCH 8
#define MTGT   64
#define NCLS   80
#define NCHAN  85
#define NPAIR  (3 * MTGT * 3)   // 576
#define MAXW   76
#define BMW    3                // bitmap words per row (76 bits -> 3 u32)

__device__ __constant__ float C_INV[3]  = {0.125f, 0.0625f, 0.03125f};
__device__ __constant__ float C_XYS[3]  = {1.2f, 1.1f, 1.05f};
__device__ __constant__ float C_AW[3][3] = {
    {1.5f, 2.375f, 5.0f},
    {2.25f, 4.75f, 4.5f},
    {4.4375f, 6.0f, 14.34375f}};
__device__ __constant__ float C_AH[3][3] = {
    {2.0f, 4.5f, 3.5f},
    {4.6875f, 3.4375f, 9.125f},
    {3.4375f, 7.59375f, 12.53125f}};

// 1 cell per thread: L0 542 blocks, L1 136, L2 34
#define NBLK0  542
#define NBLK1  136
#define NBLK2  34
#define NBLK_TOTAL (NBLK0 + NBLK1 + NBLK2)   // 712

__device__ double   g_negpart[NBLK_TOTAL];
__device__ double   g_posiou[NPAIR];
__device__ double   g_posobj[NPAIR];
__device__ double   g_poscls[NPAIR];
__device__ unsigned g_done = 0;

// ---------------------------------------------------------------------------
__device__ __forceinline__ float softplus_fast(float x) {
    return fmaxf(x, 0.0f) + __logf(1.0f + __expf(-fabsf(x)));
}

struct TPrep {
    float4 corn;   // x1,y1,x2,y2 (grid units)
    float4 cwh;    // cx, cy, wx, wy
    float  area;
    int    meta;   // bid | ti<<4 | tj<<12 | matchbits<<20
};

// EXACT fp32 (div by power-of-2 -> exact multiply), same op order as reference
__device__ __forceinline__ TPrep prep_one(int L, int t,
                                          const float* __restrict__ targets) {
    float inv = C_INV[L];
    float x1 = targets[t * 5 + 0] * inv;
    float y1 = targets[t * 5 + 1] * inv;
    float x2 = targets[t * 5 + 2] * inv;
    float y2 = targets[t * 5 + 3] * inv;
    int bid  = (int)targets[t * 5 + 4];

    float wx = x2 - x1, wy = y2 - y1;
    float cx = (x1 + x2) * 0.5f, cy = (y1 + y2) * 0.5f;
    int ti = (int)cx, tj = (int)cy;
    float tarea = wx * wy;

    float iou[3];
    #pragma unroll
    for (int a = 0; a < 3; ++a) {
        float aw = C_AW[L][a], ah = C_AH[L][a];
        float inter = fminf(aw, wx) * fminf(ah, wy);
        iou[a] = inter / ((aw * ah + tarea) - inter);   // IEEE div: threshold-critical
    }
    int best = 0;
    if (iou[1] > iou[best]) best = 1;
    if (iou[2] > iou[best]) best = 2;
    int mb = 0;
    #pragma unroll
    for (int a = 0; a < 3; ++a)
        if (iou[a] > 0.213f || a == best) mb |= (1 << a);

    TPrep p;
    p.corn = make_float4(cx - wx * 0.5f, cy - wy * 0.5f,
                         cx + wx * 0.5f, cy + wy * 0.5f);
    p.cwh  = make_float4(cx, cy, wx, wy);
    p.area = tarea;
    p.meta = bid | (ti << 4) | (tj << 12) | (mb << 20);
    return p;
}

// CIoU (forward)
__device__ __forceinline__ float ciou_f(
    float cx1, float cy1, float w1, float h1,
    float cx2, float cy2, float w2, float h2) {
    float b1x1 = cx1 - 0.5f * w1, b1x2 = cx1 + 0.5f * w1;
    float b1y1 = cy1 - 0.5f * h1, b1y2 = cy1 + 0.5f * h1;
    float b2x1 = cx2 - 0.5f * w2, b2x2 = cx2 + 0.5f * w2;
    float b2y1 = cy2 - 0.5f * h2, b2y2 = cy2 + 0.5f * h2;
    float iw = fminf(b1x2, b2x2) - fmaxf(b1x1, b2x1);
    float ih = fminf(b1y2, b2y2) - fmaxf(b1y1, b2y1);
    float inter = fmaxf(iw, 0.0f) * fmaxf(ih, 0.0f);
    float uni = w1 * h1 + w2 * h2 + 1e-16f - inter;
    float iou = inter / uni;
    float cw = fmaxf(b1x2, b2x2) - fminf(b1x1, b2x1);
    float ch = fmaxf(b1y2, b2y2) - fminf(b1y1, b2y1);
    float c2 = cw * cw + ch * ch + 1e-16f;
    float rho2 = (cx1 - cx2) * (cx1 - cx2) + (cy1 - cy2) * (cy1 - cy2);
    float d = atanf(w2 / h2) - atanf(w1 / h1);
    float v = (float)(4.0 / (M_PI * M_PI)) * d * d;
    float alpha = v / ((1.0f - iou) + v + 1e-16f);
    return iou - (rho2 / c2 + v * alpha);
}

// ---------------------------------------------------------------------------
// dense phase, templated on grid size (fast div/mod)
template<int W, int HW>
__device__ __forceinline__ float dense_cell(
    const float* __restrict__ pred, int idx, int L, float s, float half_sm1,
    const uint32_t (* __restrict__ bm)[MAXW][BMW],
    const float4* __restrict__ sc, const float* __restrict__ sa,
    const int*    __restrict__ sk, const int4*  __restrict__ spf,
    const int*    __restrict__ soff) {

    if (idx >= 24 * HW) return 0.0f;
    int plane = idx / HW;
    int lc = idx - plane * HW;
    int y = lc / W;
    int x = lc - y * W;
    int a = plane % 3;
    int b = plane / 3;
    int chan = plane * (NCHAN * HW);

    float po = pred[chan + 4 * HW + lc];   // always needed

    // O(1) candidate test
    bool zero = false;
    if ((bm[b][y][x >> 5] >> (x & 31)) & 1u) {
        float p0 = pred[chan + lc];
        float p1 = pred[chan + HW + lc];
        float p2 = pred[chan + 2 * HW + lc];
        float p3 = pred[chan + 3 * HW + lc];

        float bx = __fdividef(1.0f, 1.0f + __expf(-p0)) * s - half_sm1;
        float by = __fdividef(1.0f, 1.0f + __expf(-p1)) * s - half_sm1;
        float pw = __expf(p2) * C_AW[L][a];
        float ph = __expf(p3) * C_AH[L][a];

        float cxa = bx + (float)x;
        float cya = by + (float)y;
        float bx1 = cxa - 0.5f * pw, bx2 = cxa + 0.5f * pw;
        float by1 = cya - 0.5f * ph, by2 = cya + 0.5f * ph;
        float parea = pw * ph;

        int mykey = x | (y << 8);
        int kend = soff[b + 1];
        for (int k = soff[b]; k < kend; ++k) {
            int4 pf = spf[k];
            if (x < pf.x || x > pf.y || y < pf.z || y > pf.w) continue;
            int kk = sk[k];
            if (((kk & 0xFFFF) == mykey) && ((kk >> (16 + a)) & 1)) { zero = true; break; }
            float4 c  = sc[k];
            float ix = fminf(bx2, c.z) - fmaxf(bx1, c.x);
            float iy = fminf(by2, c.w) - fmaxf(by1, c.y);
            float inter = fmaxf(ix, 0.0f) * fmaxf(iy, 0.0f);
            float uni   = (parea + sa[k] + 1e-16f) - inter;
            if (inter > 0.7f * uni) { zero = true; break; }
        }
    }
    return zero ? 0.0f : softplus_fast(po);
}

// ---------------------------------------------------------------------------
__global__ void __launch_bounds__(256) yolo_fused_kernel(
    const float* __restrict__ pred0,
    const float* __restrict__ pred1,
    const float* __restrict__ pred2,
    const float* __restrict__ targets,
    const int*   __restrict__ cats,
    float* __restrict__ out) {

    int L, blk;
    if (blockIdx.x >= NBLK0 + NBLK1)      { L = 2; blk = blockIdx.x - (NBLK0 + NBLK1); }
    else if (blockIdx.x >= NBLK0)         { L = 1; blk = blockIdx.x - NBLK0; }
    else                                  { L = 0; blk = blockIdx.x; }

    const float* pred = (L == 0) ? pred0 : ((L == 1) ? pred1 : pred2);
    int W_rt = (L == 0) ? 76 : ((L == 1) ? 38 : 19);
    float s = C_XYS[L];
    float half_sm1 = 0.5f * (s - 1.0f);

    int tid  = threadIdx.x;
    int lane = tid & 31;
    int wid  = tid >> 5;

    // ---- shared ------------------------------------------------------------
    __shared__ uint32_t s_bm[NBATCH][MAXW][BMW];   // candidate bitmap (7.3 KB)
    __shared__ float4 s_corn[MTGT];
    __shared__ float  s_area[MTGT];
    __shared__ int    s_key [MTGT];
    __shared__ int4   s_pf  [MTGT];                // xlo,xhi,ylo,yhi
    __shared__ int    s_cnt[NBATCH], s_fill[NBATCH], s_off[NBATCH + 1];

    for (int i = tid; i < NBATCH * MAXW * BMW; i += 256)
        ((uint32_t*)s_bm)[i] = 0u;
    if (tid < NBATCH) { s_cnt[tid] = 0; s_fill[tid] = 0; }
    __syncthreads();

    // prep + bitmap paint
    TPrep myp;
    int4 mybox;
    if (tid < MTGT) {
        myp = prep_one(L, tid, targets);
        int b = myp.meta & 15;
        atomicAdd(&s_cnt[b], 1);
        // conservative candidate box: IoU>0.7 forces pred center within
        // target +/- 0.32*dim; cell within pred center +/- 1.1 scale offset.
        float tw = myp.cwh.z, th = myp.cwh.w;
        float mx = 0.34f * tw + 1.3f;
        float my = 0.34f * th + 1.3f;
        int xlo = max(0,        (int)floorf(myp.corn.x - mx));
        int xhi = min(W_rt - 1, (int)ceilf (myp.corn.z + mx));
        int ylo = max(0,        (int)floorf(myp.corn.y - my));
        int yhi = min(W_rt - 1, (int)ceilf (myp.corn.w + my));
        mybox = make_int4(xlo, xhi, ylo, yhi);
        if (xlo <= xhi) {
            int w0 = xlo >> 5, w1 = xhi >> 5;
            for (int yy = ylo; yy <= yhi; ++yy)
                for (int ww = w0; ww <= w1; ++ww) {
                    int lob = (ww == w0) ? (xlo & 31) : 0;
                    int hib = (ww == w1) ? (xhi & 31) : 31;
                    uint32_t bits = (hib == 31) ? (~0u << lob)
                                                : (((1u << (hib + 1)) - 1u) & (~0u << lob));
                    atomicOr(&s_bm[b][yy][ww], bits);
                }
        }
    }
    __syncthreads();
    if (tid == 0) {
        int acc = 0;
        #pragma unroll
        for (int i = 0; i < NBATCH; ++i) { s_off[i] = acc; acc += s_cnt[i]; }
        s_off[NBATCH] = acc;
    }
    __syncthreads();
    if (tid < MTGT) {
        int b = myp.meta & 15;
        int pos = s_off[b] + atomicAdd(&s_fill[b], 1);
        s_corn[pos] = myp.corn;
        s_area[pos] = myp.area;
        s_key [pos] = ((myp.meta >> 4) & 255) | (((myp.meta >> 12) & 255) << 8)
                    | (((myp.meta >> 20) & 7) << 16);
        s_pf [pos]  = mybox;
    }
    __syncthreads();

    // ---- dense phase: 1 cell per thread -------------------------------------
    float local;
    int idx = blk * 256 + tid;
    if (L == 0)
        local = dense_cell<76, 5776>(pred, idx, 0, s, half_sm1,
                                     s_bm, s_corn, s_area, s_key, s_pf, s_off);
    else if (L == 1)
        local = dense_cell<38, 1444>(pred, idx, 1, s, half_sm1,
                                     s_bm, s_corn, s_area, s_key, s_pf, s_off);
    else
        local = dense_cell<19, 361>(pred, idx, 2, s, half_sm1,
                                    s_bm, s_corn, s_area, s_key, s_pf, s_off);

    // ---- block reduce (double, deterministic) -------------------------------
    {
        double v = (double)local;
        #pragma unroll
        for (int o = 16; o > 0; o >>= 1)
            v += __shfl_down_sync(0xFFFFFFFFu, v, o);
        __shared__ double wsum[8];
        if (lane == 0) wsum[wid] = v;
        __syncthreads();
        if (tid == 0) {
            double t2 = 0.0;
            #pragma unroll
            for (int i = 0; i < 8; ++i) t2 += wsum[i];
            g_negpart[blockIdx.x] = t2;
        }
    }

    // ---- positives: one warp per (L,t,a) pair --------------------------------
    int gw = blockIdx.x * 8 + wid;
    if (gw < NPAIR) {
        int FL  = gw / (MTGT * 3);
        int rem = gw % (MTGT * 3);
        int t   = rem / 3;
        int a   = rem % 3;

        TPrep pp = prep_one(FL, t, targets);   // uniform across lanes
        bool matched = (pp.meta >> (20 + a)) & 1;

        double iou_d = 0.0, obj_d = 0.0, cls_d = 0.0;
        if (matched) {
            int bid = pp.meta & 15;
            int ti  = (pp.meta >> 4) & 255;
            int tj  = (pp.meta >> 12) & 255;
            const float* fp = (FL == 0) ? pred0 : ((FL == 1) ? pred1 : pred2);
            int fw  = (FL == 0) ? 76 : ((FL == 1) ? 38 : 19);
            int fhw = fw * fw;
            int base = ((bid * 3 + a) * NCHAN) * fhw + tj * fw + ti;

            float cls_acc = 0.0f;
            int cat = cats[t] - 1;
            for (int c = lane; c < NCLS; c += 32) {
                float xl  = fp[base + (5 + c) * fhw];
                float bce = softplus_fast(xl);
                if (c == cat) bce -= xl;
                cls_acc += bce;
            }
            #pragma unroll
            for (int o = 16; o > 0; o >>= 1)
                cls_acc += __shfl_down_sync(0xFFFFFFFFu, cls_acc, o);

            if (lane == 0) {
                float fs  = C_XYS[FL];
                float fhs = 0.5f * (fs - 1.0f);
                float p0 = fp[base];
                float p1 = fp[base + fhw];
                float p2 = fp[base + 2 * fhw];
                float p3 = fp[base + 3 * fhw];
                float po = fp[base + 4 * fhw];

                float bx = __fdividef(1.0f, 1.0f + __expf(-p0)) * fs - fhs;
                float by = __fdividef(1.0f, 1.0f + __expf(-p1)) * fs - fhs;
                float pw = __expf(p2) * C_AW[FL][a];
                float ph = __expf(p3) * C_AH[FL][a];

                float fx = pp.cwh.x - (float)ti;
                float fy = pp.cwh.y - (float)tj;
                iou_d = (double)(1.0f - ciou_f(bx, by, pw, ph, fx, fy,
                                               pp.cwh.z, pp.cwh.w));
                obj_d = (double)(softplus_fast(po) - po);
                cls_d = (double)cls_acc;
            }
        }
        if (lane == 0) {
            g_posiou[gw] = iou_d;
            g_posobj[gw] = obj_d;
            g_poscls[gw] = cls_d;
        }
    }

    // ---- elect last block -----------------------------------------------------
    __shared__ int s_last;
    if (tid == 0) {
        __threadfence();
        unsigned old = atomicAdd(&g_done, 1u);
        s_last = (old == NBLK_TOTAL - 1) ? 1 : 0;
    }
    __syncthreads();
    if (!s_last) return;
    __threadfence();

    // ---- final reduction (last block) -------------------------------------------
    double iou_s = 0.0, obj_s = 0.0, cls_s = 0.0, neg_s = 0.0;
    for (int i = tid; i < NBLK_TOTAL; i += 256) neg_s += g_negpart[i];
    for (int i = tid; i < NPAIR; i += 256) {
        iou_s += g_posiou[i];
        obj_s += g_posobj[i];
        cls_s += g_poscls[i];
    }

    __shared__ double fred[8][4];
    double vals[4] = {iou_s, obj_s, cls_s, neg_s};
    #pragma unroll
    for (int q = 0; q < 4; ++q) {
        double v = vals[q];
        #pragma unroll
        for (int o = 16; o > 0; o >>= 1)
            v += __shfl_down_sync(0xFFFFFFFFu, v, o);
        if (lane == 0) fred[wid][q] = v;
    }
    __syncthreads();
    if (tid == 0) {
        double tot[4] = {0.0, 0.0, 0.0, 0.0};
        #pragma unroll
        for (int i = 0; i < 8; ++i) {
            tot[0] += fred[i][0];
            tot[1] += fred[i][1];
            tot[2] += fred[i][2];
            tot[3] += fred[i][3];
        }
        out[0] = (float)(0.07 * tot[0]);
        out[1] = (float)(tot[1] + tot[3]);
        out[2] = (float)(tot[2]);
        g_done = 0;
    }
}

// ---------------------------------------------------------------------------
extern "C" void kernel_launch(void* const* d_in, const int* in_sizes, int n_in,
                              void* d_out, int out_size) {
    const float* pred0   = (const float*)d_in[0];
    const float* pred1   = (const float*)d_in[1];
    const float* pred2   = (const float*)d_in[2];
    const float* targets = (const float*)d_in[3];
    const int*   cats    = (const int*)  d_in[4];
    float* out = (float*)d_out;

    yolo_fused_kernel<<<NBLK_TOTAL, 256>>>(pred0, pred1, pred2, targets, cats, out);
}